// round 7
// baseline (speedup 1.0000x reference)
#include <cuda_runtime.h>
#include <cstdint>
#include <cstddef>

#define NN 100000
#define EE 1000000
#define DD 64
#define KK 8
#define LL 3

#define SCAN_TPB 1024
#define SCAN_BLOCKS ((NN + SCAN_TPB - 1) / SCAN_TPB)   // 98
#define NBINS 64

// ---------------- device scratch (statically allocated; no runtime alloc) ----------------
__device__ float g_T[7][(size_t)NN * DD];
__device__ float g_out1[(size_t)NN * DD];
__device__ float g_out2[(size_t)NN * DD];
__device__ float g_xp[(size_t)NN * DD];     // x permuted into degree-sorted space
__device__ float g_deg[NN];
__device__ float g_dinv[NN];
__device__ int   g_cnt[NN];                 // in-degree by original node id
__device__ int   g_cntp[NN];                // in-degree by permuted id
__device__ int   g_rowstart[NN + 1];        // CSR rowstart (permuted space)
__device__ int   g_cursor[NN];
__device__ int   g_bsum[SCAN_BLOCKS + 32];
__device__ int   g_dbins[NBINS];
__device__ int   g_dcur[NBINS];
__device__ int   g_perm[NN];                // perm[g] = original id
__device__ int   g_rank[NN];                // rank[orig] = g
__device__ float2 g_adj[EE];                // (src_rank_as_float_bits, norm)

// ---------------- normalization ----------------
__global__ void deg_hist_kernel(const int* __restrict__ src, const int* __restrict__ dst,
                                const float* __restrict__ w,
                                float* __restrict__ deg, int* __restrict__ cnt) {
    int e = blockIdx.x * blockDim.x + threadIdx.x;
    if (e >= EE) return;
    int s = src[e], d = dst[e];
    float ww = (s == d) ? 0.0f : w[e];
    if (ww != 0.0f) atomicAdd(&deg[s], ww);
    atomicAdd(&cnt[d], 1);
}

__global__ void dinv_binhist_kernel(const float* __restrict__ deg, const int* __restrict__ cnt,
                                    float* __restrict__ dinv, int* __restrict__ dbins) {
    int i = blockIdx.x * blockDim.x + threadIdx.x;
    if (i >= NN) return;
    float d = deg[i];
    dinv[i] = (d > 0.0f) ? rsqrtf(d) : 0.0f;
    atomicAdd(&dbins[min(cnt[i], NBINS - 1)], 1);
}

__global__ void bin_scan_kernel(const int* __restrict__ dbins, int* __restrict__ dcur) {
    __shared__ int s[NBINS];
    int t = threadIdx.x;
    int v = dbins[t];
    s[t] = v;
    __syncthreads();
#pragma unroll
    for (int off = 1; off < NBINS; off <<= 1) {
        int tt = (t >= off) ? s[t - off] : 0;
        __syncthreads();
        s[t] += tt;
        __syncthreads();
    }
    dcur[t] = s[t] - v;
}

__global__ void bin_scatter_kernel(const int* __restrict__ cnt, int* __restrict__ dcur,
                                   int* __restrict__ perm, int* __restrict__ rank,
                                   int* __restrict__ cntp) {
    int i = blockIdx.x * blockDim.x + threadIdx.x;
    if (i >= NN) return;
    int c = cnt[i];
    int pos = atomicAdd(&dcur[min(c, NBINS - 1)], 1);
    perm[pos] = i;
    rank[i] = pos;
    cntp[pos] = c;
}

// x_p[g] = x[perm[g]]
__global__ void permute_x_kernel(const float* __restrict__ x, const int* __restrict__ perm,
                                 float* __restrict__ xp) {
    unsigned tid = blockIdx.x * blockDim.x + threadIdx.x;
    unsigned g = tid >> 4;
    if (g >= NN) return;
    unsigned lane = tid & 15u;
    int n = perm[g];
    reinterpret_cast<float4*>(xp)[(size_t)g * 16 + lane] =
        reinterpret_cast<const float4*>(x)[(size_t)n * 16 + lane];
}

// ---------------- scan (exclusive) of cntp -> rowstart ----------------
__global__ void scan_block_kernel(const int* __restrict__ cnt, int* __restrict__ rowstart,
                                  int* __restrict__ bsum) {
    __shared__ int s[SCAN_TPB];
    int i = blockIdx.x * SCAN_TPB + threadIdx.x;
    int v = (i < NN) ? cnt[i] : 0;
    s[threadIdx.x] = v;
    __syncthreads();
#pragma unroll
    for (int off = 1; off < SCAN_TPB; off <<= 1) {
        int t = (threadIdx.x >= off) ? s[threadIdx.x - off] : 0;
        __syncthreads();
        s[threadIdx.x] += t;
        __syncthreads();
    }
    if (i <= NN) rowstart[i] = s[threadIdx.x] - v;
    if (threadIdx.x == SCAN_TPB - 1) bsum[blockIdx.x] = s[threadIdx.x];
}

__global__ void scan_sums_kernel(int* __restrict__ bsum) {
    __shared__ int s[128];
    int t = threadIdx.x;
    int v = (t < SCAN_BLOCKS) ? bsum[t] : 0;
    s[t] = v;
    __syncthreads();
#pragma unroll
    for (int off = 1; off < 128; off <<= 1) {
        int tt = (t >= off) ? s[t - off] : 0;
        __syncthreads();
        s[t] += tt;
        __syncthreads();
    }
    if (t < SCAN_BLOCKS) bsum[t] = s[t] - v;
}

__global__ void scan_add_kernel(int* __restrict__ rowstart, const int* __restrict__ bsum,
                                int* __restrict__ cursor) {
    int i = blockIdx.x * blockDim.x + threadIdx.x;
    if (i > NN) return;
    int r = rowstart[i] + bsum[i / SCAN_TPB];
    rowstart[i] = r;
    if (i < NN) cursor[i] = r;
}

// Scatter edges into permuted CSR; src stored as rank.
__global__ void scatter_kernel(const int* __restrict__ src, const int* __restrict__ dst,
                               const float* __restrict__ w, const float* __restrict__ dinv,
                               const int* __restrict__ rank,
                               int* __restrict__ cursor, float2* __restrict__ adj) {
    int e = blockIdx.x * blockDim.x + threadIdx.x;
    if (e >= EE) return;
    int s = src[e], d = dst[e];
    float ww = (s == d) ? 0.0f : w[e];
    float nrm = -dinv[s] * ww * dinv[d];
    int pos = atomicAdd(&cursor[rank[d]], 1);
    adj[pos] = make_float2(__int_as_float(rank[s]), nrm);
}

// ---------------- CSR gather propagation (r4-proven version) ----------------
template <bool FIRST>
__global__ __launch_bounds__(256)
void prop16_kernel(const float* __restrict__ h, const float2* __restrict__ adj,
                   const int* __restrict__ rowstart, const float* __restrict__ t0,
                   float* __restrict__ out) {
    unsigned tid = blockIdx.x * blockDim.x + threadIdx.x;
    unsigned n = tid >> 4;
    if (n >= NN) return;
    unsigned lane = tid & 15u;
    int r0 = rowstart[n];
    int r1 = rowstart[n + 1];

    float4 acc = make_float4(0.f, 0.f, 0.f, 0.f);
    const float4* hb = reinterpret_cast<const float4*>(h);

    int e = r0;
#pragma unroll 1
    for (; e + 3 < r1; e += 4) {
        float2 p0 = __ldg(&adj[e]);
        float2 p1 = __ldg(&adj[e + 1]);
        float2 p2 = __ldg(&adj[e + 2]);
        float2 p3 = __ldg(&adj[e + 3]);
        float4 v0 = hb[(size_t)__float_as_int(p0.x) * 16 + lane];
        float4 v1 = hb[(size_t)__float_as_int(p1.x) * 16 + lane];
        float4 v2 = hb[(size_t)__float_as_int(p2.x) * 16 + lane];
        float4 v3 = hb[(size_t)__float_as_int(p3.x) * 16 + lane];
        acc.x = fmaf(p0.y, v0.x, acc.x); acc.y = fmaf(p0.y, v0.y, acc.y);
        acc.z = fmaf(p0.y, v0.z, acc.z); acc.w = fmaf(p0.y, v0.w, acc.w);
        acc.x = fmaf(p1.y, v1.x, acc.x); acc.y = fmaf(p1.y, v1.y, acc.y);
        acc.z = fmaf(p1.y, v1.z, acc.z); acc.w = fmaf(p1.y, v1.w, acc.w);
        acc.x = fmaf(p2.y, v2.x, acc.x); acc.y = fmaf(p2.y, v2.y, acc.y);
        acc.z = fmaf(p2.y, v2.z, acc.z); acc.w = fmaf(p2.y, v2.w, acc.w);
        acc.x = fmaf(p3.y, v3.x, acc.x); acc.y = fmaf(p3.y, v3.y, acc.y);
        acc.z = fmaf(p3.y, v3.z, acc.z); acc.w = fmaf(p3.y, v3.w, acc.w);
    }
#pragma unroll 1
    for (; e < r1; e++) {
        float2 p0 = __ldg(&adj[e]);
        float4 v0 = hb[(size_t)__float_as_int(p0.x) * 16 + lane];
        acc.x = fmaf(p0.y, v0.x, acc.x); acc.y = fmaf(p0.y, v0.y, acc.y);
        acc.z = fmaf(p0.y, v0.z, acc.z); acc.w = fmaf(p0.y, v0.w, acc.w);
    }

    size_t idx = (size_t)n * 16 + lane;
    if (FIRST) {
        reinterpret_cast<float4*>(out)[idx] = acc;
    } else {
        float4 t = reinterpret_cast<const float4*>(t0)[idx];
        reinterpret_cast<float4*>(out)[idx] =
            make_float4(2.0f * acc.x - t.x, 2.0f * acc.y - t.y,
                        2.0f * acc.z - t.z, 2.0f * acc.w - t.w);
    }
}

// ---------------- fused 8-way GEMM + bias + relu, packed f32x2 (the A/B change) ----------------
struct TPtrs { const float* p[KK]; };

#define FMA2(a, v, w) asm("fma.rn.f32x2 %0, %1, %2, %0;" : "+l"(a) : "l"(v), "l"(w))
#define DUP2(d, f)    asm("mov.b64 %0, {%1, %1};" : "=l"(d) : "f"(f))
#define UNPK(lo, hi, a) asm("mov.b64 {%0, %1}, %2;" : "=f"(lo), "=f"(hi) : "l"(a))

__global__ __launch_bounds__(256)
void gemm8_kernel(TPtrs ts, const float* __restrict__ W,
                  const float* __restrict__ bias, float* __restrict__ out,
                  const int* __restrict__ operm) {
    __shared__ float Xs[128][DD];      // swizzled at float4 granularity
    __shared__ float Ws[DD][DD];
    int tid = threadIdx.x;
    int row0 = blockIdx.x * 128;
    int tx = tid & 3, ty = tid >> 2;

    unsigned long long acc0[8], acc1[8];
#pragma unroll
    for (int i = 0; i < 8; i++) { acc0[i] = 0ull; acc1[i] = 0ull; }

    for (int k = 0; k < KK; ++k) {
        const float* X = ts.p[k];
        const float* Wp = W + (size_t)k * DD * DD;
#pragma unroll
        for (int i = 0; i < 4; i++) {
            int f4 = tid + i * 256;
            int j = f4 >> 4, c4 = f4 & 15;
            reinterpret_cast<float4*>(&Ws[j][0])[c4] =
                reinterpret_cast<const float4*>(Wp)[f4];
        }
#pragma unroll
        for (int i = 0; i < 8; i++) {
            int f4 = tid + i * 256;
            int r = f4 >> 4, c4 = f4 & 15;
            int sc4 = (c4 + (r >> 1)) & 15;
            int gr = row0 + r;
            float4 v = make_float4(0.f, 0.f, 0.f, 0.f);
            if (gr < NN) v = reinterpret_cast<const float4*>(X + (size_t)gr * DD)[c4];
            reinterpret_cast<float4*>(&Xs[r][0])[sc4] = v;
        }
        __syncthreads();

#pragma unroll 8
        for (int j = 0; j < DD; j++) {
            int sc4 = ((j >> 2) + ty) & 15;
            int col = sc4 * 4 + (j & 3);
            float a0 = Xs[ty * 2 + 0][col];
            float a1 = Xs[ty * 2 + 1][col];
            unsigned long long A0, A1;
            DUP2(A0, a0);
            DUP2(A1, a1);
            const ulonglong2* bp = reinterpret_cast<const ulonglong2*>(&Ws[j][tx * 16]);
            ulonglong2 b01 = bp[0], b23 = bp[1], b45 = bp[2], b67 = bp[3];
            FMA2(acc0[0], A0, b01.x); FMA2(acc0[1], A0, b01.y);
            FMA2(acc0[2], A0, b23.x); FMA2(acc0[3], A0, b23.y);
            FMA2(acc0[4], A0, b45.x); FMA2(acc0[5], A0, b45.y);
            FMA2(acc0[6], A0, b67.x); FMA2(acc0[7], A0, b67.y);
            FMA2(acc1[0], A1, b01.x); FMA2(acc1[1], A1, b01.y);
            FMA2(acc1[2], A1, b23.x); FMA2(acc1[3], A1, b23.y);
            FMA2(acc1[4], A1, b45.x); FMA2(acc1[5], A1, b45.y);
            FMA2(acc1[6], A1, b67.x); FMA2(acc1[7], A1, b67.y);
        }
        __syncthreads();
    }

    float bv[16];
#pragma unroll
    for (int q = 0; q < 4; q++) {
        float4 b4 = reinterpret_cast<const float4*>(bias)[tx * 4 + q];
        bv[q * 4 + 0] = b4.x; bv[q * 4 + 1] = b4.y;
        bv[q * 4 + 2] = b4.z; bv[q * 4 + 3] = b4.w;
    }
#pragma unroll
    for (int hh = 0; hh < 2; hh++) {
        int gr = row0 + ty * 2 + hh;
        if (gr >= NN) continue;
        int orow = operm ? operm[gr] : gr;
        unsigned long long* acc = hh ? acc1 : acc0;
#pragma unroll
        for (int q = 0; q < 4; q++) {
            float x0, x1, x2, x3;
            UNPK(x0, x1, acc[2 * q]);
            UNPK(x2, x3, acc[2 * q + 1]);
            float4 v;
            v.x = fmaxf(x0 + bv[q * 4 + 0], 0.f);
            v.y = fmaxf(x1 + bv[q * 4 + 1], 0.f);
            v.z = fmaxf(x2 + bv[q * 4 + 2], 0.f);
            v.w = fmaxf(x3 + bv[q * 4 + 3], 0.f);
            reinterpret_cast<float4*>(out + (size_t)orow * DD)[tx * 4 + q] = v;
        }
    }
}

// ---------------- launcher ----------------
extern "C" void kernel_launch(void* const* d_in, const int* in_sizes, int n_in,
                              void* d_out, int out_size) {
    const float* x  = (const float*)d_in[0];
    const int*   ei = (const int*)d_in[1];
    const float* ew = (const float*)d_in[2];
    const float* Wt = (const float*)d_in[3];
    const float* Bs = (const float*)d_in[4];
    const int* src = ei;
    const int* dst = ei + EE;

    float *Tbuf, *out1, *out2, *xp, *deg, *dinv;
    int *cnt, *cntp, *rowstart, *cursor, *bsum, *dbins, *dcur, *perm, *rank;
    float2* adj;
    cudaGetSymbolAddress((void**)&Tbuf, g_T);
    cudaGetSymbolAddress((void**)&out1, g_out1);
    cudaGetSymbolAddress((void**)&out2, g_out2);
    cudaGetSymbolAddress((void**)&xp, g_xp);
    cudaGetSymbolAddress((void**)&deg, g_deg);
    cudaGetSymbolAddress((void**)&dinv, g_dinv);
    cudaGetSymbolAddress((void**)&cnt, g_cnt);
    cudaGetSymbolAddress((void**)&cntp, g_cntp);
    cudaGetSymbolAddress((void**)&rowstart, g_rowstart);
    cudaGetSymbolAddress((void**)&cursor, g_cursor);
    cudaGetSymbolAddress((void**)&bsum, g_bsum);
    cudaGetSymbolAddress((void**)&dbins, g_dbins);
    cudaGetSymbolAddress((void**)&dcur, g_dcur);
    cudaGetSymbolAddress((void**)&perm, g_perm);
    cudaGetSymbolAddress((void**)&rank, g_rank);
    cudaGetSymbolAddress((void**)&adj, g_adj);

    const size_t FB = (size_t)NN * DD;
    float* TB[7];
    for (int i = 0; i < 7; i++) TB[i] = Tbuf + (size_t)i * FB;

    const int T = 256;
    const int edgeBlocks = (EE + T - 1) / T;
    const int nodeBlocks = (NN + T - 1) / T;
    const int node1Blocks = (NN + 1 + T - 1) / T;
    const int propBlocks = (NN * 16 + T - 1) / T;
    const int gemmBlocks = (NN + 127) / 128;

    // --- setup: degrees, sort, permuted CSR, permuted x ---
    cudaMemsetAsync(deg, 0, NN * sizeof(float));
    cudaMemsetAsync(cnt, 0, NN * sizeof(int));
    cudaMemsetAsync(dbins, 0, NBINS * sizeof(int));
    deg_hist_kernel<<<edgeBlocks, T>>>(src, dst, ew, deg, cnt);
    dinv_binhist_kernel<<<nodeBlocks, T>>>(deg, cnt, dinv, dbins);
    bin_scan_kernel<<<1, NBINS>>>(dbins, dcur);
    bin_scatter_kernel<<<nodeBlocks, T>>>(cnt, dcur, perm, rank, cntp);
    scan_block_kernel<<<SCAN_BLOCKS, SCAN_TPB>>>(cntp, rowstart, bsum);
    scan_sums_kernel<<<1, 128>>>(bsum);
    scan_add_kernel<<<node1Blocks, T>>>(rowstart, bsum, cursor);
    scatter_kernel<<<edgeBlocks, T>>>(src, dst, ew, dinv, rank, cursor, adj);
    permute_x_kernel<<<propBlocks, T>>>(x, perm, xp);

    // --- layers (all buffers in permuted space) ---
    const float* hin = xp;
    float* houts[3] = {out1, out2, (float*)d_out};

    for (int l = 0; l < LL; l++) {
        const float* Wl = Wt + (size_t)l * KK * DD * DD;
        prop16_kernel<true><<<propBlocks, T>>>(hin, adj, rowstart, nullptr, TB[0]);
        for (int k = 2; k < KK; k++) {
            const float* tin = TB[k - 2];
            const float* t0 = (k == 2) ? hin : TB[k - 3];
            prop16_kernel<false><<<propBlocks, T>>>(tin, adj, rowstart, t0, TB[k - 1]);
        }
        TPtrs ts;
        ts.p[0] = hin;
        for (int k = 1; k < KK; k++) ts.p[k] = TB[k - 1];
        const int* operm = (l == LL - 1) ? perm : nullptr;
        gemm8_kernel<<<gemmBlocks, T>>>(ts, Wl, Bs + (size_t)l * DD, houts[l], operm);
        hin = houts[l];
    }
}

// round 8
// speedup vs baseline: 1.5223x; 1.5223x over previous
#include <cuda_runtime.h>
#include <cstdint>
#include <cstddef>

#define NN 100000
#define EE 1000000
#define DD 64
#define KK 8
#define LL 3

#define SCAN_TPB 1024
#define SCAN_BLOCKS ((NN + SCAN_TPB - 1) / SCAN_TPB)   // 98
#define NBINS 64

// ---------------- device scratch (statically allocated; no runtime alloc) ----------------
__device__ float g_T[7][(size_t)NN * DD];
__device__ float g_out1[(size_t)NN * DD];
__device__ float g_out2[(size_t)NN * DD];
__device__ float g_xp[(size_t)NN * DD];     // x permuted into degree-sorted space
__device__ float g_deg[NN];
__device__ float g_dinv[NN];
__device__ int   g_cnt[NN];                 // in-degree by original node id
__device__ int   g_cntp[NN];                // in-degree by permuted id
__device__ int   g_rowstart[NN + 1];        // CSR rowstart (permuted space)
__device__ int   g_cursor[NN];
__device__ int   g_bsum[SCAN_BLOCKS + 32];
__device__ int   g_dbins[NBINS];
__device__ int   g_dcur[NBINS];
__device__ int   g_perm[NN];                // perm[g] = original id
__device__ int   g_rank[NN];                // rank[orig] = g
__device__ float2 g_adj[EE];                // (src_rank_as_float_bits, norm)

// ---------------- normalization ----------------
__global__ void deg_hist_kernel(const int* __restrict__ src, const int* __restrict__ dst,
                                const float* __restrict__ w,
                                float* __restrict__ deg, int* __restrict__ cnt) {
    int e = blockIdx.x * blockDim.x + threadIdx.x;
    if (e >= EE) return;
    int s = src[e], d = dst[e];
    float ww = (s == d) ? 0.0f : w[e];
    if (ww != 0.0f) atomicAdd(&deg[s], ww);
    atomicAdd(&cnt[d], 1);
}

__global__ void dinv_binhist_kernel(const float* __restrict__ deg, const int* __restrict__ cnt,
                                    float* __restrict__ dinv, int* __restrict__ dbins) {
    int i = blockIdx.x * blockDim.x + threadIdx.x;
    if (i >= NN) return;
    float d = deg[i];
    dinv[i] = (d > 0.0f) ? rsqrtf(d) : 0.0f;
    atomicAdd(&dbins[min(cnt[i], NBINS - 1)], 1);
}

__global__ void bin_scan_kernel(const int* __restrict__ dbins, int* __restrict__ dcur) {
    __shared__ int s[NBINS];
    int t = threadIdx.x;
    int v = dbins[t];
    s[t] = v;
    __syncthreads();
#pragma unroll
    for (int off = 1; off < NBINS; off <<= 1) {
        int tt = (t >= off) ? s[t - off] : 0;
        __syncthreads();
        s[t] += tt;
        __syncthreads();
    }
    dcur[t] = s[t] - v;
}

__global__ void bin_scatter_kernel(const int* __restrict__ cnt, int* __restrict__ dcur,
                                   int* __restrict__ perm, int* __restrict__ rank,
                                   int* __restrict__ cntp) {
    int i = blockIdx.x * blockDim.x + threadIdx.x;
    if (i >= NN) return;
    int c = cnt[i];
    int pos = atomicAdd(&dcur[min(c, NBINS - 1)], 1);
    perm[pos] = i;
    rank[i] = pos;
    cntp[pos] = c;
}

// x_p[g] = x[perm[g]]
__global__ void permute_x_kernel(const float* __restrict__ x, const int* __restrict__ perm,
                                 float* __restrict__ xp) {
    unsigned tid = blockIdx.x * blockDim.x + threadIdx.x;
    unsigned g = tid >> 4;
    if (g >= NN) return;
    unsigned lane = tid & 15u;
    int n = perm[g];
    reinterpret_cast<float4*>(xp)[(size_t)g * 16 + lane] =
        reinterpret_cast<const float4*>(x)[(size_t)n * 16 + lane];
}

// ---------------- scan (exclusive) of cntp -> rowstart ----------------
__global__ void scan_block_kernel(const int* __restrict__ cnt, int* __restrict__ rowstart,
                                  int* __restrict__ bsum) {
    __shared__ int s[SCAN_TPB];
    int i = blockIdx.x * SCAN_TPB + threadIdx.x;
    int v = (i < NN) ? cnt[i] : 0;
    s[threadIdx.x] = v;
    __syncthreads();
#pragma unroll
    for (int off = 1; off < SCAN_TPB; off <<= 1) {
        int t = (threadIdx.x >= off) ? s[threadIdx.x - off] : 0;
        __syncthreads();
        s[threadIdx.x] += t;
        __syncthreads();
    }
    if (i <= NN) rowstart[i] = s[threadIdx.x] - v;
    if (threadIdx.x == SCAN_TPB - 1) bsum[blockIdx.x] = s[threadIdx.x];
}

__global__ void scan_sums_kernel(int* __restrict__ bsum) {
    __shared__ int s[128];
    int t = threadIdx.x;
    int v = (t < SCAN_BLOCKS) ? bsum[t] : 0;
    s[t] = v;
    __syncthreads();
#pragma unroll
    for (int off = 1; off < 128; off <<= 1) {
        int tt = (t >= off) ? s[t - off] : 0;
        __syncthreads();
        s[t] += tt;
        __syncthreads();
    }
    if (t < SCAN_BLOCKS) bsum[t] = s[t] - v;
}

__global__ void scan_add_kernel(int* __restrict__ rowstart, const int* __restrict__ bsum,
                                int* __restrict__ cursor) {
    int i = blockIdx.x * blockDim.x + threadIdx.x;
    if (i > NN) return;
    int r = rowstart[i] + bsum[i / SCAN_TPB];
    rowstart[i] = r;
    if (i < NN) cursor[i] = r;
}

// Scatter edges into permuted CSR; src stored as rank.
__global__ void scatter_kernel(const int* __restrict__ src, const int* __restrict__ dst,
                               const float* __restrict__ w, const float* __restrict__ dinv,
                               const int* __restrict__ rank,
                               int* __restrict__ cursor, float2* __restrict__ adj) {
    int e = blockIdx.x * blockDim.x + threadIdx.x;
    if (e >= EE) return;
    int s = src[e], d = dst[e];
    float ww = (s == d) ? 0.0f : w[e];
    float nrm = -dinv[s] * ww * dinv[d];
    int pos = atomicAdd(&cursor[rank[d]], 1);
    adj[pos] = make_float2(__int_as_float(rank[s]), nrm);
}

// ---------------- CSR gather propagation (r4-proven version, unchanged) ----------------
template <bool FIRST>
__global__ __launch_bounds__(256)
void prop16_kernel(const float* __restrict__ h, const float2* __restrict__ adj,
                   const int* __restrict__ rowstart, const float* __restrict__ t0,
                   float* __restrict__ out) {
    unsigned tid = blockIdx.x * blockDim.x + threadIdx.x;
    unsigned n = tid >> 4;
    if (n >= NN) return;
    unsigned lane = tid & 15u;
    int r0 = rowstart[n];
    int r1 = rowstart[n + 1];

    float4 acc = make_float4(0.f, 0.f, 0.f, 0.f);
    const float4* hb = reinterpret_cast<const float4*>(h);

    int e = r0;
#pragma unroll 1
    for (; e + 3 < r1; e += 4) {
        float2 p0 = __ldg(&adj[e]);
        float2 p1 = __ldg(&adj[e + 1]);
        float2 p2 = __ldg(&adj[e + 2]);
        float2 p3 = __ldg(&adj[e + 3]);
        float4 v0 = hb[(size_t)__float_as_int(p0.x) * 16 + lane];
        float4 v1 = hb[(size_t)__float_as_int(p1.x) * 16 + lane];
        float4 v2 = hb[(size_t)__float_as_int(p2.x) * 16 + lane];
        float4 v3 = hb[(size_t)__float_as_int(p3.x) * 16 + lane];
        acc.x = fmaf(p0.y, v0.x, acc.x); acc.y = fmaf(p0.y, v0.y, acc.y);
        acc.z = fmaf(p0.y, v0.z, acc.z); acc.w = fmaf(p0.y, v0.w, acc.w);
        acc.x = fmaf(p1.y, v1.x, acc.x); acc.y = fmaf(p1.y, v1.y, acc.y);
        acc.z = fmaf(p1.y, v1.z, acc.z); acc.w = fmaf(p1.y, v1.w, acc.w);
        acc.x = fmaf(p2.y, v2.x, acc.x); acc.y = fmaf(p2.y, v2.y, acc.y);
        acc.z = fmaf(p2.y, v2.z, acc.z); acc.w = fmaf(p2.y, v2.w, acc.w);
        acc.x = fmaf(p3.y, v3.x, acc.x); acc.y = fmaf(p3.y, v3.y, acc.y);
        acc.z = fmaf(p3.y, v3.z, acc.z); acc.w = fmaf(p3.y, v3.w, acc.w);
    }
#pragma unroll 1
    for (; e < r1; e++) {
        float2 p0 = __ldg(&adj[e]);
        float4 v0 = hb[(size_t)__float_as_int(p0.x) * 16 + lane];
        acc.x = fmaf(p0.y, v0.x, acc.x); acc.y = fmaf(p0.y, v0.y, acc.y);
        acc.z = fmaf(p0.y, v0.z, acc.z); acc.w = fmaf(p0.y, v0.w, acc.w);
    }

    size_t idx = (size_t)n * 16 + lane;
    if (FIRST) {
        reinterpret_cast<float4*>(out)[idx] = acc;
    } else {
        float4 t = reinterpret_cast<const float4*>(t0)[idx];
        reinterpret_cast<float4*>(out)[idx] =
            make_float4(2.0f * acc.x - t.x, 2.0f * acc.y - t.y,
                        2.0f * acc.z - t.z, 2.0f * acc.w - t.w);
    }
}

// ---------------- fused 8-way GEMM + bias + relu (scalar FFMA, LDS.128 A-loads) ----------------
// Tile 128 rows x 64 cols, 256 threads: tx = tid&15 (float4 col group), ty = tid>>4 (8 rows).
// Xs stored with float4 rotate swizzle: chunk c4 of row r at (c4 + (r>>1)) & 15, so
// the per-i A-load (2 addresses/warp, rows r and r+8) hits different banks.
struct TPtrs { const float* p[KK]; };

__global__ __launch_bounds__(256)
void gemm8_kernel(TPtrs ts, const float* __restrict__ W,
                  const float* __restrict__ bias, float* __restrict__ out,
                  const int* __restrict__ operm) {
    __shared__ float Xs[128][DD];      // swizzled at float4 granularity
    __shared__ float Ws[DD][DD];
    int tid = threadIdx.x;
    int row0 = blockIdx.x * 128;
    int tx = tid & 15, ty = tid >> 4;

    float accR[8][4];
#pragma unroll
    for (int i = 0; i < 8; i++)
#pragma unroll
        for (int c = 0; c < 4; c++) accR[i][c] = 0.0f;

    for (int k = 0; k < KK; ++k) {
        const float* X = ts.p[k];
        const float* Wp = W + (size_t)k * DD * DD;
#pragma unroll
        for (int i = 0; i < 4; i++) {
            int f4 = tid + i * 256;          // 1024 float4s of W
            int j = f4 >> 4, c4 = f4 & 15;
            reinterpret_cast<float4*>(&Ws[j][0])[c4] =
                reinterpret_cast<const float4*>(Wp)[f4];
        }
#pragma unroll
        for (int i = 0; i < 8; i++) {
            int f4 = tid + i * 256;          // 128 rows x 16 float4
            int r = f4 >> 4, c4 = f4 & 15;
            int sc4 = (c4 + (r >> 1)) & 15;  // swizzle
            int gr = row0 + r;
            float4 v = make_float4(0.f, 0.f, 0.f, 0.f);
            if (gr < NN) v = reinterpret_cast<const float4*>(X + (size_t)gr * DD)[c4];
            reinterpret_cast<float4*>(&Xs[r][0])[sc4] = v;
        }
        __syncthreads();

#pragma unroll 4
        for (int jc = 0; jc < 16; jc++) {          // j = 4*jc .. 4*jc+3
            float4 b0 = reinterpret_cast<float4*>(&Ws[4 * jc + 0][0])[tx];
            float4 b1 = reinterpret_cast<float4*>(&Ws[4 * jc + 1][0])[tx];
            float4 b2 = reinterpret_cast<float4*>(&Ws[4 * jc + 2][0])[tx];
            float4 b3 = reinterpret_cast<float4*>(&Ws[4 * jc + 3][0])[tx];
#pragma unroll
            for (int i = 0; i < 8; i++) {
                int r = ty * 8 + i;
                int sc4 = (jc + (r >> 1)) & 15;
                float4 a4 = reinterpret_cast<float4*>(&Xs[r][0])[sc4];
                accR[i][0] = fmaf(a4.x, b0.x, accR[i][0]);
                accR[i][1] = fmaf(a4.x, b0.y, accR[i][1]);
                accR[i][2] = fmaf(a4.x, b0.z, accR[i][2]);
                accR[i][3] = fmaf(a4.x, b0.w, accR[i][3]);
                accR[i][0] = fmaf(a4.y, b1.x, accR[i][0]);
                accR[i][1] = fmaf(a4.y, b1.y, accR[i][1]);
                accR[i][2] = fmaf(a4.y, b1.z, accR[i][2]);
                accR[i][3] = fmaf(a4.y, b1.w, accR[i][3]);
                accR[i][0] = fmaf(a4.z, b2.x, accR[i][0]);
                accR[i][1] = fmaf(a4.z, b2.y, accR[i][1]);
                accR[i][2] = fmaf(a4.z, b2.z, accR[i][2]);
                accR[i][3] = fmaf(a4.z, b2.w, accR[i][3]);
                accR[i][0] = fmaf(a4.w, b3.x, accR[i][0]);
                accR[i][1] = fmaf(a4.w, b3.y, accR[i][1]);
                accR[i][2] = fmaf(a4.w, b3.z, accR[i][2]);
                accR[i][3] = fmaf(a4.w, b3.w, accR[i][3]);
            }
        }
        __syncthreads();
    }

    float4 b4 = reinterpret_cast<const float4*>(bias)[tx];
#pragma unroll
    for (int i = 0; i < 8; i++) {
        int gr = row0 + ty * 8 + i;
        if (gr < NN) {
            int orow = operm ? operm[gr] : gr;
            float4 v;
            v.x = fmaxf(accR[i][0] + b4.x, 0.f);
            v.y = fmaxf(accR[i][1] + b4.y, 0.f);
            v.z = fmaxf(accR[i][2] + b4.z, 0.f);
            v.w = fmaxf(accR[i][3] + b4.w, 0.f);
            reinterpret_cast<float4*>(out + (size_t)orow * DD)[tx] = v;
        }
    }
}

// ---------------- launcher ----------------
extern "C" void kernel_launch(void* const* d_in, const int* in_sizes, int n_in,
                              void* d_out, int out_size) {
    const float* x  = (const float*)d_in[0];
    const int*   ei = (const int*)d_in[1];
    const float* ew = (const float*)d_in[2];
    const float* Wt = (const float*)d_in[3];
    const float* Bs = (const float*)d_in[4];
    const int* src = ei;
    const int* dst = ei + EE;

    float *Tbuf, *out1, *out2, *xp, *deg, *dinv;
    int *cnt, *cntp, *rowstart, *cursor, *bsum, *dbins, *dcur, *perm, *rank;
    float2* adj;
    cudaGetSymbolAddress((void**)&Tbuf, g_T);
    cudaGetSymbolAddress((void**)&out1, g_out1);
    cudaGetSymbolAddress((void**)&out2, g_out2);
    cudaGetSymbolAddress((void**)&xp, g_xp);
    cudaGetSymbolAddress((void**)&deg, g_deg);
    cudaGetSymbolAddress((void**)&dinv, g_dinv);
    cudaGetSymbolAddress((void**)&cnt, g_cnt);
    cudaGetSymbolAddress((void**)&cntp, g_cntp);
    cudaGetSymbolAddress((void**)&rowstart, g_rowstart);
    cudaGetSymbolAddress((void**)&cursor, g_cursor);
    cudaGetSymbolAddress((void**)&bsum, g_bsum);
    cudaGetSymbolAddress((void**)&dbins, g_dbins);
    cudaGetSymbolAddress((void**)&dcur, g_dcur);
    cudaGetSymbolAddress((void**)&perm, g_perm);
    cudaGetSymbolAddress((void**)&rank, g_rank);
    cudaGetSymbolAddress((void**)&adj, g_adj);

    const size_t FB = (size_t)NN * DD;
    float* TB[7];
    for (int i = 0; i < 7; i++) TB[i] = Tbuf + (size_t)i * FB;

    const int T = 256;
    const int edgeBlocks = (EE + T - 1) / T;
    const int nodeBlocks = (NN + T - 1) / T;
    const int node1Blocks = (NN + 1 + T - 1) / T;
    const int propBlocks = (NN * 16 + T - 1) / T;
    const int gemmBlocks = (NN + 127) / 128;

    // --- setup: degrees, sort, permuted CSR, permuted x ---
    cudaMemsetAsync(deg, 0, NN * sizeof(float));
    cudaMemsetAsync(cnt, 0, NN * sizeof(int));
    cudaMemsetAsync(dbins, 0, NBINS * sizeof(int));
    deg_hist_kernel<<<edgeBlocks, T>>>(src, dst, ew, deg, cnt);
    dinv_binhist_kernel<<<nodeBlocks, T>>>(deg, cnt, dinv, dbins);
    bin_scan_kernel<<<1, NBINS>>>(dbins, dcur);
    bin_scatter_kernel<<<nodeBlocks, T>>>(cnt, dcur, perm, rank, cntp);
    scan_block_kernel<<<SCAN_BLOCKS, SCAN_TPB>>>(cntp, rowstart, bsum);
    scan_sums_kernel<<<1, 128>>>(bsum);
    scan_add_kernel<<<node1Blocks, T>>>(rowstart, bsum, cursor);
    scatter_kernel<<<edgeBlocks, T>>>(src, dst, ew, dinv, rank, cursor, adj);
    permute_x_kernel<<<propBlocks, T>>>(x, perm, xp);

    // --- layers (all buffers in permuted space) ---
    const float* hin = xp;
    float* houts[3] = {out1, out2, (float*)d_out};

    for (int l = 0; l < LL; l++) {
        const float* Wl = Wt + (size_t)l * KK * DD * DD;
        prop16_kernel<true><<<propBlocks, T>>>(hin, adj, rowstart, nullptr, TB[0]);
        for (int k = 2; k < KK; k++) {
            const float* tin = TB[k - 2];
            const float* t0 = (k == 2) ? hin : TB[k - 3];
            prop16_kernel<false><<<propBlocks, T>>>(tin, adj, rowstart, t0, TB[k - 1]);
        }
        TPtrs ts;
        ts.p[0] = hin;
        for (int k = 1; k < KK; k++) ts.p[k] = TB[k - 1];
        const int* operm = (l == LL - 1) ? perm : nullptr;
        gemm8_kernel<<<gemmBlocks, T>>>(ts, Wl, Bs + (size_t)l * DD, houts[l], operm);
        hin = houts[l];
    }
}

// round 11
// speedup vs baseline: 1.9829x; 1.3026x over previous
#include <cuda_runtime.h>
#include <cuda_bf16.h>
#include <cstdint>
#include <cstddef>

#define NN 100000
#define EE 1000000
#define DD 64
#define KK 8
#define LL 3

#define SCAN_TPB 1024
#define SCAN_BLOCKS ((NN + SCAN_TPB - 1) / SCAN_TPB)   // 98
#define NBINS 64

// ---------------- device scratch ----------------
__device__ float g_T[7][(size_t)NN * DD];
__device__ float g_out1[(size_t)NN * DD];
__device__ float g_out2[(size_t)NN * DD];
__device__ float g_xp[(size_t)NN * DD];
__device__ float g_deg[NN];
__device__ float g_dinv[NN];
__device__ int   g_cnt[NN];
__device__ int   g_cntp[NN];
__device__ int   g_rowstart[NN + 1];
__device__ int   g_cursor[NN];
__device__ int   g_bsum[SCAN_BLOCKS + 32];
__device__ int   g_dbins[NBINS];
__device__ int   g_dcur[NBINS];
__device__ int   g_perm[NN];
__device__ int   g_rank[NN];
__device__ float2 g_adj[EE];
// W pre-converted per (l,k) slice: 4096 bf16 hi then 4096 bf16 lo, layout [n][kk].
__device__ __align__(16) __nv_bfloat16 g_Wc[LL * KK * 2 * DD * DD];

// ---------------- normalization / CSR / sort (r8-proven, unchanged) ----------------
__global__ void deg_hist_kernel(const int* __restrict__ src, const int* __restrict__ dst,
                                const float* __restrict__ w,
                                float* __restrict__ deg, int* __restrict__ cnt) {
    int e = blockIdx.x * blockDim.x + threadIdx.x;
    if (e >= EE) return;
    int s = src[e], d = dst[e];
    float ww = (s == d) ? 0.0f : w[e];
    if (ww != 0.0f) atomicAdd(&deg[s], ww);
    atomicAdd(&cnt[d], 1);
}

__global__ void dinv_binhist_kernel(const float* __restrict__ deg, const int* __restrict__ cnt,
                                    float* __restrict__ dinv, int* __restrict__ dbins) {
    int i = blockIdx.x * blockDim.x + threadIdx.x;
    if (i >= NN) return;
    float d = deg[i];
    dinv[i] = (d > 0.0f) ? rsqrtf(d) : 0.0f;
    atomicAdd(&dbins[min(cnt[i], NBINS - 1)], 1);
}

__global__ void bin_scan_kernel(const int* __restrict__ dbins, int* __restrict__ dcur) {
    __shared__ int s[NBINS];
    int t = threadIdx.x;
    int v = dbins[t];
    s[t] = v;
    __syncthreads();
#pragma unroll
    for (int off = 1; off < NBINS; off <<= 1) {
        int tt = (t >= off) ? s[t - off] : 0;
        __syncthreads();
        s[t] += tt;
        __syncthreads();
    }
    dcur[t] = s[t] - v;
}

__global__ void bin_scatter_kernel(const int* __restrict__ cnt, int* __restrict__ dcur,
                                   int* __restrict__ perm, int* __restrict__ rank,
                                   int* __restrict__ cntp) {
    int i = blockIdx.x * blockDim.x + threadIdx.x;
    if (i >= NN) return;
    int c = cnt[i];
    int pos = atomicAdd(&dcur[min(c, NBINS - 1)], 1);
    perm[pos] = i;
    rank[i] = pos;
    cntp[pos] = c;
}

__global__ void permute_x_kernel(const float* __restrict__ x, const int* __restrict__ perm,
                                 float* __restrict__ xp) {
    unsigned tid = blockIdx.x * blockDim.x + threadIdx.x;
    unsigned g = tid >> 4;
    if (g >= NN) return;
    unsigned lane = tid & 15u;
    int n = perm[g];
    reinterpret_cast<float4*>(xp)[(size_t)g * 16 + lane] =
        reinterpret_cast<const float4*>(x)[(size_t)n * 16 + lane];
}

__global__ void scan_block_kernel(const int* __restrict__ cnt, int* __restrict__ rowstart,
                                  int* __restrict__ bsum) {
    __shared__ int s[SCAN_TPB];
    int i = blockIdx.x * SCAN_TPB + threadIdx.x;
    int v = (i < NN) ? cnt[i] : 0;
    s[threadIdx.x] = v;
    __syncthreads();
#pragma unroll
    for (int off = 1; off < SCAN_TPB; off <<= 1) {
        int t = (threadIdx.x >= off) ? s[threadIdx.x - off] : 0;
        __syncthreads();
        s[threadIdx.x] += t;
        __syncthreads();
    }
    if (i <= NN) rowstart[i] = s[threadIdx.x] - v;
    if (threadIdx.x == SCAN_TPB - 1) bsum[blockIdx.x] = s[threadIdx.x];
}

__global__ void scan_sums_kernel(int* __restrict__ bsum) {
    __shared__ int s[128];
    int t = threadIdx.x;
    int v = (t < SCAN_BLOCKS) ? bsum[t] : 0;
    s[t] = v;
    __syncthreads();
#pragma unroll
    for (int off = 1; off < 128; off <<= 1) {
        int tt = (t >= off) ? s[t - off] : 0;
        __syncthreads();
        s[t] += tt;
        __syncthreads();
    }
    if (t < SCAN_BLOCKS) bsum[t] = s[t] - v;
}

__global__ void scan_add_kernel(int* __restrict__ rowstart, const int* __restrict__ bsum,
                                int* __restrict__ cursor) {
    int i = blockIdx.x * blockDim.x + threadIdx.x;
    if (i > NN) return;
    int r = rowstart[i] + bsum[i / SCAN_TPB];
    rowstart[i] = r;
    if (i < NN) cursor[i] = r;
}

__global__ void scatter_kernel(const int* __restrict__ src, const int* __restrict__ dst,
                               const float* __restrict__ w, const float* __restrict__ dinv,
                               const int* __restrict__ rank,
                               int* __restrict__ cursor, float2* __restrict__ adj) {
    int e = blockIdx.x * blockDim.x + threadIdx.x;
    if (e >= EE) return;
    int s = src[e], d = dst[e];
    float ww = (s == d) ? 0.0f : w[e];
    float nrm = -dinv[s] * ww * dinv[d];
    int pos = atomicAdd(&cursor[rank[d]], 1);
    adj[pos] = make_float2(__int_as_float(rank[s]), nrm);
}

// W conversion: per slice, hi[n][kk] then lo[n][kk] (bf16). B[n][kk] = W[kk][n].
__global__ void convw_kernel(const float* __restrict__ Wt, __nv_bfloat16* __restrict__ Wc) {
    int idx = blockIdx.x * blockDim.x + threadIdx.x;
    if (idx >= LL * KK * DD * DD) return;
    int n = idx & 63;
    int kk = (idx >> 6) & 63;
    int slice = idx >> 12;
    float w = Wt[(size_t)slice * 4096 + kk * 64 + n];
    __nv_bfloat16 hi = __float2bfloat16(w);
    __nv_bfloat16 lo = __float2bfloat16(w - __bfloat162float(hi));
    __nv_bfloat16* base = Wc + (size_t)slice * 8192;
    base[n * 64 + kk] = hi;
    base[4096 + n * 64 + kk] = lo;
}

// ---------------- CSR gather propagation (r8-proven, unchanged) ----------------
template <bool FIRST>
__global__ __launch_bounds__(256)
void prop16_kernel(const float* __restrict__ h, const float2* __restrict__ adj,
                   const int* __restrict__ rowstart, const float* __restrict__ t0,
                   float* __restrict__ out) {
    unsigned tid = blockIdx.x * blockDim.x + threadIdx.x;
    unsigned n = tid >> 4;
    if (n >= NN) return;
    unsigned lane = tid & 15u;
    int r0 = rowstart[n];
    int r1 = rowstart[n + 1];

    float4 acc = make_float4(0.f, 0.f, 0.f, 0.f);
    const float4* hb = reinterpret_cast<const float4*>(h);

    int e = r0;
#pragma unroll 1
    for (; e + 3 < r1; e += 4) {
        float2 p0 = __ldg(&adj[e]);
        float2 p1 = __ldg(&adj[e + 1]);
        float2 p2 = __ldg(&adj[e + 2]);
        float2 p3 = __ldg(&adj[e + 3]);
        float4 v0 = hb[(size_t)__float_as_int(p0.x) * 16 + lane];
        float4 v1 = hb[(size_t)__float_as_int(p1.x) * 16 + lane];
        float4 v2 = hb[(size_t)__float_as_int(p2.x) * 16 + lane];
        float4 v3 = hb[(size_t)__float_as_int(p3.x) * 16 + lane];
        acc.x = fmaf(p0.y, v0.x, acc.x); acc.y = fmaf(p0.y, v0.y, acc.y);
        acc.z = fmaf(p0.y, v0.z, acc.z); acc.w = fmaf(p0.y, v0.w, acc.w);
        acc.x = fmaf(p1.y, v1.x, acc.x); acc.y = fmaf(p1.y, v1.y, acc.y);
        acc.z = fmaf(p1.y, v1.z, acc.z); acc.w = fmaf(p1.y, v1.w, acc.w);
        acc.x = fmaf(p2.y, v2.x, acc.x); acc.y = fmaf(p2.y, v2.y, acc.y);
        acc.z = fmaf(p2.y, v2.z, acc.z); acc.w = fmaf(p2.y, v2.w, acc.w);
        acc.x = fmaf(p3.y, v3.x, acc.x); acc.y = fmaf(p3.y, v3.y, acc.y);
        acc.z = fmaf(p3.y, v3.z, acc.z); acc.w = fmaf(p3.y, v3.w, acc.w);
    }
#pragma unroll 1
    for (; e < r1; e++) {
        float2 p0 = __ldg(&adj[e]);
        float4 v0 = hb[(size_t)__float_as_int(p0.x) * 16 + lane];
        acc.x = fmaf(p0.y, v0.x, acc.x); acc.y = fmaf(p0.y, v0.y, acc.y);
        acc.z = fmaf(p0.y, v0.z, acc.z); acc.w = fmaf(p0.y, v0.w, acc.w);
    }

    size_t idx = (size_t)n * 16 + lane;
    if (FIRST) {
        reinterpret_cast<float4*>(out)[idx] = acc;
    } else {
        float4 t = reinterpret_cast<const float4*>(t0)[idx];
        reinterpret_cast<float4*>(out)[idx] =
            make_float4(2.0f * acc.x - t.x, 2.0f * acc.y - t.y,
                        2.0f * acc.z - t.z, 2.0f * acc.w - t.w);
    }
}

// ---------------- mma.sync bf16 hi/lo-split GEMM + bias + relu ----------------
// Block 256 thr (8 warps), tile 128 rows x 64 cols. Warp w: rows 16w..16w+15.
// mma.sync.aligned.m16n8k16.row.col.f32.bf16.bf16.f32 (sm_80+, no 'a' suffix).
struct TPtrs { const float* p[KK]; };

#define PADROW 144               // 72 bf16 = 144 bytes per smem row
#define SM_XHI  0                // [128][72] bf16
#define SM_XLO  18432
#define SM_WHI  36864            // [64][72] bf16
#define SM_WLO  46080
#define SM_TOTAL 55296

#define MMA_BF16(c, a0, a1, a2, a3, b0, b1) \
    asm volatile("mma.sync.aligned.m16n8k16.row.col.f32.bf16.bf16.f32 " \
                 "{%0,%1,%2,%3}, {%4,%5,%6,%7}, {%8,%9}, {%0,%1,%2,%3};" \
                 : "+f"((c)[0]), "+f"((c)[1]), "+f"((c)[2]), "+f"((c)[3]) \
                 : "r"(a0), "r"(a1), "r"(a2), "r"(a3), "r"(b0), "r"(b1))

__global__ __launch_bounds__(256)
void gemm_mma_kernel(TPtrs ts, const __nv_bfloat16* __restrict__ Wc_layer,
                     const float* __restrict__ bias, float* __restrict__ out,
                     const int* __restrict__ operm) {
    extern __shared__ __align__(16) char smem[];
    int tid = threadIdx.x;
    int w = tid >> 5;
    int lane = tid & 31;
    int gid = lane >> 2;          // 0..7
    int tig = lane & 3;           // 0..3
    int row0 = blockIdx.x * 128;
    int rA = w * 16 + gid;        // tile-local row for fragment (and rA+8)

    float acc[8][4];
#pragma unroll
    for (int nt = 0; nt < 8; nt++)
#pragma unroll
        for (int c = 0; c < 4; c++) acc[nt][c] = 0.0f;

    for (int s = 0; s < KK; ++s) {
        if (s > 0) __syncthreads();   // all warps done reading prev slice's smem

        // stage X -> bf16 hi/lo [128][72]
        const float4* Xv = reinterpret_cast<const float4*>(ts.p[s]);
#pragma unroll
        for (int i = 0; i < 8; i++) {
            int idx = tid + i * 256;          // 2048 float4 chunks
            int r = idx >> 4, c4 = idx & 15;
            int gr = row0 + r;
            float4 v = make_float4(0.f, 0.f, 0.f, 0.f);
            if (gr < NN) v = Xv[(size_t)gr * 16 + c4];
            __nv_bfloat162 h01 = __floats2bfloat162_rn(v.x, v.y);
            __nv_bfloat162 h23 = __floats2bfloat162_rn(v.z, v.w);
            float2 f01 = __bfloat1622float2(h01);
            float2 f23 = __bfloat1622float2(h23);
            __nv_bfloat162 l01 = __floats2bfloat162_rn(v.x - f01.x, v.y - f01.y);
            __nv_bfloat162 l23 = __floats2bfloat162_rn(v.z - f23.x, v.w - f23.y);
            uint32_t off = (uint32_t)r * PADROW + (uint32_t)c4 * 8;
            *reinterpret_cast<__nv_bfloat162*>(smem + SM_XHI + off) = h01;
            *reinterpret_cast<__nv_bfloat162*>(smem + SM_XHI + off + 4) = h23;
            *reinterpret_cast<__nv_bfloat162*>(smem + SM_XLO + off) = l01;
            *reinterpret_cast<__nv_bfloat162*>(smem + SM_XLO + off + 4) = l23;
        }
        // stage W hi+lo: 2048 uint2 from global [64][64]x2 into [64][72]x2
        const uint2* Wg = reinterpret_cast<const uint2*>(Wc_layer) + (size_t)s * 2048;
#pragma unroll
        for (int i = 0; i < 8; i++) {
            int idx = tid + i * 256;
            int half = idx >> 10;             // 0=hi, 1=lo
            int j = idx & 1023;
            int n = j >> 4, c = j & 15;
            uint2 val = Wg[idx];
            *reinterpret_cast<uint2*>(smem + (half ? SM_WLO : SM_WHI)
                                      + (uint32_t)n * PADROW + (uint32_t)c * 8) = val;
        }
        __syncthreads();

        // compute
#pragma unroll
        for (int kstep = 0; kstep < 4; kstep++) {
            uint32_t acol = (uint32_t)(kstep * 16 + 2 * tig) * 2;
            const char* axh = smem + SM_XHI + (uint32_t)rA * PADROW + acol;
            const char* axl = smem + SM_XLO + (uint32_t)rA * PADROW + acol;
            uint32_t ah0 = *reinterpret_cast<const uint32_t*>(axh);
            uint32_t ah1 = *reinterpret_cast<const uint32_t*>(axh + 8 * PADROW);
            uint32_t ah2 = *reinterpret_cast<const uint32_t*>(axh + 16);
            uint32_t ah3 = *reinterpret_cast<const uint32_t*>(axh + 8 * PADROW + 16);
            uint32_t al0 = *reinterpret_cast<const uint32_t*>(axl);
            uint32_t al1 = *reinterpret_cast<const uint32_t*>(axl + 8 * PADROW);
            uint32_t al2 = *reinterpret_cast<const uint32_t*>(axl + 16);
            uint32_t al3 = *reinterpret_cast<const uint32_t*>(axl + 8 * PADROW + 16);
#pragma unroll
            for (int nt = 0; nt < 8; nt++) {
                uint32_t boff = (uint32_t)(nt * 8 + gid) * PADROW + acol;
                uint32_t bh0 = *reinterpret_cast<const uint32_t*>(smem + SM_WHI + boff);
                uint32_t bh1 = *reinterpret_cast<const uint32_t*>(smem + SM_WHI + boff + 16);
                uint32_t bl0 = *reinterpret_cast<const uint32_t*>(smem + SM_WLO + boff);
                uint32_t bl1 = *reinterpret_cast<const uint32_t*>(smem + SM_WLO + boff + 16);
                MMA_BF16(acc[nt], ah0, ah1, ah2, ah3, bh0, bh1);
                MMA_BF16(acc[nt], al0, al1, al2, al3, bh0, bh1);
                MMA_BF16(acc[nt], ah0, ah1, ah2, ah3, bl0, bl1);
            }
        }
    }

    // epilogue: rows row0+rA (c0,c1) and row0+rA+8 (c2,c3); cols nt*8 + 2*tig, +1
    int gr1 = row0 + rA;
    int gr2 = gr1 + 8;
    int or1 = (gr1 < NN) ? (operm ? operm[gr1] : gr1) : -1;
    int or2 = (gr2 < NN) ? (operm ? operm[gr2] : gr2) : -1;
#pragma unroll
    for (int nt = 0; nt < 8; nt++) {
        int col = nt * 8 + 2 * tig;
        float b0 = bias[col], b1 = bias[col + 1];
        if (or1 >= 0) {
            float2 v;
            v.x = fmaxf(acc[nt][0] + b0, 0.f);
            v.y = fmaxf(acc[nt][1] + b1, 0.f);
            *reinterpret_cast<float2*>(out + (size_t)or1 * DD + col) = v;
        }
        if (or2 >= 0) {
            float2 v;
            v.x = fmaxf(acc[nt][2] + b0, 0.f);
            v.y = fmaxf(acc[nt][3] + b1, 0.f);
            *reinterpret_cast<float2*>(out + (size_t)or2 * DD + col) = v;
        }
    }
}

// ---------------- launcher ----------------
extern "C" void kernel_launch(void* const* d_in, const int* in_sizes, int n_in,
                              void* d_out, int out_size) {
    const float* x  = (const float*)d_in[0];
    const int*   ei = (const int*)d_in[1];
    const float* ew = (const float*)d_in[2];
    const float* Wt = (const float*)d_in[3];
    const float* Bs = (const float*)d_in[4];
    const int* src = ei;
    const int* dst = ei + EE;

    float *Tbuf, *out1, *out2, *xp, *deg, *dinv;
    int *cnt, *cntp, *rowstart, *cursor, *bsum, *dbins, *dcur, *perm, *rank;
    float2* adj;
    __nv_bfloat16* Wc;
    cudaGetSymbolAddress((void**)&Tbuf, g_T);
    cudaGetSymbolAddress((void**)&out1, g_out1);
    cudaGetSymbolAddress((void**)&out2, g_out2);
    cudaGetSymbolAddress((void**)&xp, g_xp);
    cudaGetSymbolAddress((void**)&deg, g_deg);
    cudaGetSymbolAddress((void**)&dinv, g_dinv);
    cudaGetSymbolAddress((void**)&cnt, g_cnt);
    cudaGetSymbolAddress((void**)&cntp, g_cntp);
    cudaGetSymbolAddress((void**)&rowstart, g_rowstart);
    cudaGetSymbolAddress((void**)&cursor, g_cursor);
    cudaGetSymbolAddress((void**)&bsum, g_bsum);
    cudaGetSymbolAddress((void**)&dbins, g_dbins);
    cudaGetSymbolAddress((void**)&dcur, g_dcur);
    cudaGetSymbolAddress((void**)&perm, g_perm);
    cudaGetSymbolAddress((void**)&rank, g_rank);
    cudaGetSymbolAddress((void**)&adj, g_adj);
    cudaGetSymbolAddress((void**)&Wc, g_Wc);

    static int smem_set = 0;
    if (!smem_set) {
        cudaFuncSetAttribute(gemm_mma_kernel,
                             cudaFuncAttributeMaxDynamicSharedMemorySize, SM_TOTAL);
        smem_set = 1;
    }

    const size_t FB = (size_t)NN * DD;
    float* TB[7];
    for (int i = 0; i < 7; i++) TB[i] = Tbuf + (size_t)i * FB;

    const int T = 256;
    const int edgeBlocks = (EE + T - 1) / T;
    const int nodeBlocks = (NN + T - 1) / T;
    const int node1Blocks = (NN + 1 + T - 1) / T;
    const int propBlocks = (NN * 16 + T - 1) / T;
    const int gemmBlocks = (NN + 127) / 128;
    const int convwBlocks = (LL * KK * DD * DD + T - 1) / T;

    // --- setup ---
    cudaMemsetAsync(deg, 0, NN * sizeof(float));
    cudaMemsetAsync(cnt, 0, NN * sizeof(int));
    cudaMemsetAsync(dbins, 0, NBINS * sizeof(int));
    deg_hist_kernel<<<edgeBlocks, T>>>(src, dst, ew, deg, cnt);
    dinv_binhist_kernel<<<nodeBlocks, T>>>(deg, cnt, dinv, dbins);
    bin_scan_kernel<<<1, NBINS>>>(dbins, dcur);
    bin_scatter_kernel<<<nodeBlocks, T>>>(cnt, dcur, perm, rank, cntp);
    scan_block_kernel<<<SCAN_BLOCKS, SCAN_TPB>>>(cntp, rowstart, bsum);
    scan_sums_kernel<<<1, 128>>>(bsum);
    scan_add_kernel<<<node1Blocks, T>>>(rowstart, bsum, cursor);
    scatter_kernel<<<edgeBlocks, T>>>(src, dst, ew, dinv, rank, cursor, adj);
    permute_x_kernel<<<propBlocks, T>>>(x, perm, xp);
    convw_kernel<<<convwBlocks, T>>>(Wt, Wc);

    // --- layers ---
    const float* hin = xp;
    float* houts[3] = {out1, out2, (float*)d_out};

    for (int l = 0; l < LL; l++) {
        prop16_kernel<true><<<propBlocks, T>>>(hin, adj, rowstart, nullptr, TB[0]);
        for (int k = 2; k < KK; k++) {
            const float* tin = TB[k - 2];
            const float* t0 = (k == 2) ? hin : TB[k - 3];
            prop16_kernel<false><<<propBlocks, T>>>(tin, adj, rowstart, t0, TB[k - 1]);
        }
        TPtrs tsp;
        tsp.p[0] = hin;
        for (int k = 1; k < KK; k++) tsp.p[k] = TB[k - 1];
        const int* operm = (l == LL - 1) ? perm : nullptr;
        gemm_mma_kernel<<<gemmBlocks, 256, SM_TOTAL>>>(
            tsp, Wc + (size_t)l * KK * 2 * DD * DD, Bs + (size_t)l * DD,
            houts[l], operm);
        hin = houts[l];
    }
}

// round 12
// speedup vs baseline: 2.0467x; 1.0322x over previous
#include <cuda_runtime.h>
#include <cuda_bf16.h>
#include <cstdint>
#include <cstddef>

#define NN 100000
#define EE 1000000
#define DD 64
#define KK 8
#define LL 3

#define SCAN_TPB 1024
#define SCAN_BLOCKS ((NN + SCAN_TPB - 1) / SCAN_TPB)   // 98
#define NBINS 64

// ---------------- device scratch ----------------
__device__ float g_T[7][(size_t)NN * DD];
__device__ float g_out1[(size_t)NN * DD];
__device__ float g_out2[(size_t)NN * DD];
__device__ float g_xp[(size_t)NN * DD];
__device__ float g_deg[NN];
__device__ float g_dinv[NN];
__device__ int   g_cnt[NN];
__device__ int   g_cntp[NN];
__device__ int   g_rowstart[NN + 1];
__device__ int   g_cursor[NN];
__device__ int   g_bsum[SCAN_BLOCKS + 32];
__device__ int   g_dbins[NBINS];
__device__ int   g_dcur[NBINS];
__device__ int   g_perm[NN];
__device__ int   g_rank[NN];
__device__ float2 g_adj[EE];
// W pre-converted per (l,k) slice: 4096 bf16 hi then 4096 bf16 lo, layout [n][kk].
__device__ __align__(16) __nv_bfloat16 g_Wc[LL * KK * 2 * DD * DD];

// ---------------- normalization / CSR / sort ----------------
__global__ void deg_hist_kernel(const int* __restrict__ src, const int* __restrict__ dst,
                                const float* __restrict__ w,
                                float* __restrict__ deg, int* __restrict__ cnt) {
    int e = blockIdx.x * blockDim.x + threadIdx.x;
    if (e >= EE) return;
    int s = src[e], d = dst[e];
    float ww = (s == d) ? 0.0f : w[e];
    if (ww != 0.0f) atomicAdd(&deg[s], ww);
    atomicAdd(&cnt[d], 1);
}

__global__ void dinv_binhist_kernel(const float* __restrict__ deg, const int* __restrict__ cnt,
                                    float* __restrict__ dinv, int* __restrict__ dbins) {
    int i = blockIdx.x * blockDim.x + threadIdx.x;
    if (i >= NN) return;
    float d = deg[i];
    dinv[i] = (d > 0.0f) ? rsqrtf(d) : 0.0f;
    atomicAdd(&dbins[min(cnt[i], NBINS - 1)], 1);
}

__global__ void bin_scan_kernel(const int* __restrict__ dbins, int* __restrict__ dcur) {
    __shared__ int s[NBINS];
    int t = threadIdx.x;
    int v = dbins[t];
    s[t] = v;
    __syncthreads();
#pragma unroll
    for (int off = 1; off < NBINS; off <<= 1) {
        int tt = (t >= off) ? s[t - off] : 0;
        __syncthreads();
        s[t] += tt;
        __syncthreads();
    }
    dcur[t] = s[t] - v;
}

// block-aggregated scatter: smem histogram, one global atomic per bin per block
__global__ __launch_bounds__(256)
void bin_scatter_kernel(const int* __restrict__ cnt, int* __restrict__ dcur,
                        int* __restrict__ perm, int* __restrict__ rank,
                        int* __restrict__ cntp) {
    __shared__ int localCnt[NBINS];
    __shared__ int localBase[NBINS];
    int tid = threadIdx.x;
    if (tid < NBINS) localCnt[tid] = 0;
    __syncthreads();
    int i = blockIdx.x * blockDim.x + tid;
    int c = 0, b = 0, lpos = 0;
    bool valid = (i < NN);
    if (valid) {
        c = cnt[i];
        b = min(c, NBINS - 1);
        lpos = atomicAdd(&localCnt[b], 1);
    }
    __syncthreads();
    if (tid < NBINS && localCnt[tid] > 0)
        localBase[tid] = atomicAdd(&dcur[tid], localCnt[tid]);
    __syncthreads();
    if (valid) {
        int pos = localBase[b] + lpos;
        perm[pos] = i;
        rank[i] = pos;
        cntp[pos] = c;
    }
}

__global__ void permute_x_kernel(const float* __restrict__ x, const int* __restrict__ perm,
                                 float* __restrict__ xp) {
    unsigned tid = blockIdx.x * blockDim.x + threadIdx.x;
    unsigned g = tid >> 4;
    if (g >= NN) return;
    unsigned lane = tid & 15u;
    int n = perm[g];
    reinterpret_cast<float4*>(xp)[(size_t)g * 16 + lane] =
        reinterpret_cast<const float4*>(x)[(size_t)n * 16 + lane];
}

__global__ void scan_block_kernel(const int* __restrict__ cnt, int* __restrict__ rowstart,
                                  int* __restrict__ bsum) {
    __shared__ int s[SCAN_TPB];
    int i = blockIdx.x * SCAN_TPB + threadIdx.x;
    int v = (i < NN) ? cnt[i] : 0;
    s[threadIdx.x] = v;
    __syncthreads();
#pragma unroll
    for (int off = 1; off < SCAN_TPB; off <<= 1) {
        int t = (threadIdx.x >= off) ? s[threadIdx.x - off] : 0;
        __syncthreads();
        s[threadIdx.x] += t;
        __syncthreads();
    }
    if (i <= NN) rowstart[i] = s[threadIdx.x] - v;
    if (threadIdx.x == SCAN_TPB - 1) bsum[blockIdx.x] = s[threadIdx.x];
}

__global__ void scan_sums_kernel(int* __restrict__ bsum) {
    __shared__ int s[128];
    int t = threadIdx.x;
    int v = (t < SCAN_BLOCKS) ? bsum[t] : 0;
    s[t] = v;
    __syncthreads();
#pragma unroll
    for (int off = 1; off < 128; off <<= 1) {
        int tt = (t >= off) ? s[t - off] : 0;
        __syncthreads();
        s[t] += tt;
        __syncthreads();
    }
    if (t < SCAN_BLOCKS) bsum[t] = s[t] - v;
}

__global__ void scan_add_kernel(int* __restrict__ rowstart, const int* __restrict__ bsum,
                                int* __restrict__ cursor) {
    int i = blockIdx.x * blockDim.x + threadIdx.x;
    if (i > NN) return;
    int r = rowstart[i] + bsum[i / SCAN_TPB];
    rowstart[i] = r;
    if (i < NN) cursor[i] = r;
}

__global__ void scatter_kernel(const int* __restrict__ src, const int* __restrict__ dst,
                               const float* __restrict__ w, const float* __restrict__ dinv,
                               const int* __restrict__ rank,
                               int* __restrict__ cursor, float2* __restrict__ adj) {
    int e = blockIdx.x * blockDim.x + threadIdx.x;
    if (e >= EE) return;
    int s = src[e], d = dst[e];
    float ww = (s == d) ? 0.0f : w[e];
    float nrm = -dinv[s] * ww * dinv[d];
    int pos = atomicAdd(&cursor[rank[d]], 1);
    adj[pos] = make_float2(__int_as_float(rank[s]), nrm);
}

// W conversion: per slice, hi[n][kk] then lo[n][kk] (bf16). B[n][kk] = W[kk][n].
__global__ void convw_kernel(const float* __restrict__ Wt, __nv_bfloat16* __restrict__ Wc) {
    int idx = blockIdx.x * blockDim.x + threadIdx.x;
    if (idx >= LL * KK * DD * DD) return;
    int n = idx & 63;
    int kk = (idx >> 6) & 63;
    int slice = idx >> 12;
    float w = Wt[(size_t)slice * 4096 + kk * 64 + n];
    __nv_bfloat16 hi = __float2bfloat16(w);
    __nv_bfloat16 lo = __float2bfloat16(w - __bfloat162float(hi));
    __nv_bfloat16* base = Wc + (size_t)slice * 8192;
    base[n * 64 + kk] = hi;
    base[4096 + n * 64 + kk] = lo;
}

// ---------------- CSR gather propagation (unroll 8 for MLP) ----------------
#define EDGE_FMA(p, v) do { \
    acc.x = fmaf((p).y, (v).x, acc.x); acc.y = fmaf((p).y, (v).y, acc.y); \
    acc.z = fmaf((p).y, (v).z, acc.z); acc.w = fmaf((p).y, (v).w, acc.w); \
} while (0)

template <bool FIRST>
__global__ __launch_bounds__(256)
void prop16_kernel(const float* __restrict__ h, const float2* __restrict__ adj,
                   const int* __restrict__ rowstart, const float* __restrict__ t0,
                   float* __restrict__ out) {
    unsigned tid = blockIdx.x * blockDim.x + threadIdx.x;
    unsigned n = tid >> 4;
    if (n >= NN) return;
    unsigned lane = tid & 15u;
    int r0 = rowstart[n];
    int r1 = rowstart[n + 1];

    float4 acc = make_float4(0.f, 0.f, 0.f, 0.f);
    const float4* hb = reinterpret_cast<const float4*>(h);

    int e = r0;
#pragma unroll 1
    for (; e + 7 < r1; e += 8) {
        float2 p0 = __ldg(&adj[e]);
        float2 p1 = __ldg(&adj[e + 1]);
        float2 p2 = __ldg(&adj[e + 2]);
        float2 p3 = __ldg(&adj[e + 3]);
        float2 p4 = __ldg(&adj[e + 4]);
        float2 p5 = __ldg(&adj[e + 5]);
        float2 p6 = __ldg(&adj[e + 6]);
        float2 p7 = __ldg(&adj[e + 7]);
        float4 v0 = hb[(size_t)__float_as_int(p0.x) * 16 + lane];
        float4 v1 = hb[(size_t)__float_as_int(p1.x) * 16 + lane];
        float4 v2 = hb[(size_t)__float_as_int(p2.x) * 16 + lane];
        float4 v3 = hb[(size_t)__float_as_int(p3.x) * 16 + lane];
        float4 v4 = hb[(size_t)__float_as_int(p4.x) * 16 + lane];
        float4 v5 = hb[(size_t)__float_as_int(p5.x) * 16 + lane];
        float4 v6 = hb[(size_t)__float_as_int(p6.x) * 16 + lane];
        float4 v7 = hb[(size_t)__float_as_int(p7.x) * 16 + lane];
        EDGE_FMA(p0, v0); EDGE_FMA(p1, v1); EDGE_FMA(p2, v2); EDGE_FMA(p3, v3);
        EDGE_FMA(p4, v4); EDGE_FMA(p5, v5); EDGE_FMA(p6, v6); EDGE_FMA(p7, v7);
    }
#pragma unroll 1
    for (; e + 3 < r1; e += 4) {
        float2 p0 = __ldg(&adj[e]);
        float2 p1 = __ldg(&adj[e + 1]);
        float2 p2 = __ldg(&adj[e + 2]);
        float2 p3 = __ldg(&adj[e + 3]);
        float4 v0 = hb[(size_t)__float_as_int(p0.x) * 16 + lane];
        float4 v1 = hb[(size_t)__float_as_int(p1.x) * 16 + lane];
        float4 v2 = hb[(size_t)__float_as_int(p2.x) * 16 + lane];
        float4 v3 = hb[(size_t)__float_as_int(p3.x) * 16 + lane];
        EDGE_FMA(p0, v0); EDGE_FMA(p1, v1); EDGE_FMA(p2, v2); EDGE_FMA(p3, v3);
    }
#pragma unroll 1
    for (; e < r1; e++) {
        float2 p0 = __ldg(&adj[e]);
        float4 v0 = hb[(size_t)__float_as_int(p0.x) * 16 + lane];
        EDGE_FMA(p0, v0);
    }

    size_t idx = (size_t)n * 16 + lane;
    if (FIRST) {
        reinterpret_cast<float4*>(out)[idx] = acc;
    } else {
        float4 t = reinterpret_cast<const float4*>(t0)[idx];
        reinterpret_cast<float4*>(out)[idx] =
            make_float4(2.0f * acc.x - t.x, 2.0f * acc.y - t.y,
                        2.0f * acc.z - t.z, 2.0f * acc.w - t.w);
    }
}

// ---------------- mma.sync bf16 hi/lo-split GEMM + bias + relu (r11-proven) ----------------
struct TPtrs { const float* p[KK]; };

#define PADROW 144               // 72 bf16 = 144 bytes per smem row
#define SM_XHI  0                // [128][72] bf16
#define SM_XLO  18432
#define SM_WHI  36864            // [64][72] bf16
#define SM_WLO  46080
#define SM_TOTAL 55296

#define MMA_BF16(c, a0, a1, a2, a3, b0, b1) \
    asm volatile("mma.sync.aligned.m16n8k16.row.col.f32.bf16.bf16.f32 " \
                 "{%0,%1,%2,%3}, {%4,%5,%6,%7}, {%8,%9}, {%0,%1,%2,%3};" \
                 : "+f"((c)[0]), "+f"((c)[1]), "+f"((c)[2]), "+f"((c)[3]) \
                 : "r"(a0), "r"(a1), "r"(a2), "r"(a3), "r"(b0), "r"(b1))

__global__ __launch_bounds__(256)
void gemm_mma_kernel(TPtrs ts, const __nv_bfloat16* __restrict__ Wc_layer,
                     const float* __restrict__ bias, float* __restrict__ out,
                     const int* __restrict__ operm) {
    extern __shared__ __align__(16) char smem[];
    int tid = threadIdx.x;
    int w = tid >> 5;
    int lane = tid & 31;
    int gid = lane >> 2;
    int tig = lane & 3;
    int row0 = blockIdx.x * 128;
    int rA = w * 16 + gid;

    float acc[8][4];
#pragma unroll
    for (int nt = 0; nt < 8; nt++)
#pragma unroll
        for (int c = 0; c < 4; c++) acc[nt][c] = 0.0f;

    for (int s = 0; s < KK; ++s) {
        if (s > 0) __syncthreads();

        const float4* Xv = reinterpret_cast<const float4*>(ts.p[s]);
#pragma unroll
        for (int i = 0; i < 8; i++) {
            int idx = tid + i * 256;
            int r = idx >> 4, c4 = idx & 15;
            int gr = row0 + r;
            float4 v = make_float4(0.f, 0.f, 0.f, 0.f);
            if (gr < NN) v = Xv[(size_t)gr * 16 + c4];
            __nv_bfloat162 h01 = __floats2bfloat162_rn(v.x, v.y);
            __nv_bfloat162 h23 = __floats2bfloat162_rn(v.z, v.w);
            float2 f01 = __bfloat1622float2(h01);
            float2 f23 = __bfloat1622float2(h23);
            __nv_bfloat162 l01 = __floats2bfloat162_rn(v.x - f01.x, v.y - f01.y);
            __nv_bfloat162 l23 = __floats2bfloat162_rn(v.z - f23.x, v.w - f23.y);
            uint32_t off = (uint32_t)r * PADROW + (uint32_t)c4 * 8;
            *reinterpret_cast<__nv_bfloat162*>(smem + SM_XHI + off) = h01;
            *reinterpret_cast<__nv_bfloat162*>(smem + SM_XHI + off + 4) = h23;
            *reinterpret_cast<__nv_bfloat162*>(smem + SM_XLO + off) = l01;
            *reinterpret_cast<__nv_bfloat162*>(smem + SM_XLO + off + 4) = l23;
        }
        const uint2* Wg = reinterpret_cast<const uint2*>(Wc_layer) + (size_t)s * 2048;
#pragma unroll
        for (int i = 0; i < 8; i++) {
            int idx = tid + i * 256;
            int half = idx >> 10;
            int j = idx & 1023;
            int n = j >> 4, c = j & 15;
            uint2 val = Wg[idx];
            *reinterpret_cast<uint2*>(smem + (half ? SM_WLO : SM_WHI)
                                      + (uint32_t)n * PADROW + (uint32_t)c * 8) = val;
        }
        __syncthreads();

#pragma unroll
        for (int kstep = 0; kstep < 4; kstep++) {
            uint32_t acol = (uint32_t)(kstep * 16 + 2 * tig) * 2;
            const char* axh = smem + SM_XHI + (uint32_t)rA * PADROW + acol;
            const char* axl = smem + SM_XLO + (uint32_t)rA * PADROW + acol;
            uint32_t ah0 = *reinterpret_cast<const uint32_t*>(axh);
            uint32_t ah1 = *reinterpret_cast<const uint32_t*>(axh + 8 * PADROW);
            uint32_t ah2 = *reinterpret_cast<const uint32_t*>(axh + 16);
            uint32_t ah3 = *reinterpret_cast<const uint32_t*>(axh + 8 * PADROW + 16);
            uint32_t al0 = *reinterpret_cast<const uint32_t*>(axl);
            uint32_t al1 = *reinterpret_cast<const uint32_t*>(axl + 8 * PADROW);
            uint32_t al2 = *reinterpret_cast<const uint32_t*>(axl + 16);
            uint32_t al3 = *reinterpret_cast<const uint32_t*>(axl + 8 * PADROW + 16);
#pragma unroll
            for (int nt = 0; nt < 8; nt++) {
                uint32_t boff = (uint32_t)(nt * 8 + gid) * PADROW + acol;
                uint32_t bh0 = *reinterpret_cast<const uint32_t*>(smem + SM_WHI + boff);
                uint32_t bh1 = *reinterpret_cast<const uint32_t*>(smem + SM_WHI + boff + 16);
                uint32_t bl0 = *reinterpret_cast<const uint32_t*>(smem + SM_WLO + boff);
                uint32_t bl1 = *reinterpret_cast<const uint32_t*>(smem + SM_WLO + boff + 16);
                MMA_BF16(acc[nt], ah0, ah1, ah2, ah3, bh0, bh1);
                MMA_BF16(acc[nt], al0, al1, al2, al3, bh0, bh1);
                MMA_BF16(acc[nt], ah0, ah1, ah2, ah3, bl0, bl1);
            }
        }
    }

    int gr1 = row0 + rA;
    int gr2 = gr1 + 8;
    int or1 = (gr1 < NN) ? (operm ? operm[gr1] : gr1) : -1;
    int or2 = (gr2 < NN) ? (operm ? operm[gr2] : gr2) : -1;
#pragma unroll
    for (int nt = 0; nt < 8; nt++) {
        int col = nt * 8 + 2 * tig;
        float b0 = bias[col], b1 = bias[col + 1];
        if (or1 >= 0) {
            float2 v;
            v.x = fmaxf(acc[nt][0] + b0, 0.f);
            v.y = fmaxf(acc[nt][1] + b1, 0.f);
            *reinterpret_cast<float2*>(out + (size_t)or1 * DD + col) = v;
        }
        if (or2 >= 0) {
            float2 v;
            v.x = fmaxf(acc[nt][2] + b0, 0.f);
            v.y = fmaxf(acc[nt][3] + b1, 0.f);
            *reinterpret_cast<float2*>(out + (size_t)or2 * DD + col) = v;
        }
    }
}

// ---------------- launcher ----------------
extern "C" void kernel_launch(void* const* d_in, const int* in_sizes, int n_in,
                              void* d_out, int out_size) {
    const float* x  = (const float*)d_in[0];
    const int*   ei = (const int*)d_in[1];
    const float* ew = (const float*)d_in[2];
    const float* Wt = (const float*)d_in[3];
    const float* Bs = (const float*)d_in[4];
    const int* src = ei;
    const int* dst = ei + EE;

    float *Tbuf, *out1, *out2, *xp, *deg, *dinv;
    int *cnt, *cntp, *rowstart, *cursor, *bsum, *dbins, *dcur, *perm, *rank;
    float2* adj;
    __nv_bfloat16* Wc;
    cudaGetSymbolAddress((void**)&Tbuf, g_T);
    cudaGetSymbolAddress((void**)&out1, g_out1);
    cudaGetSymbolAddress((void**)&out2, g_out2);
    cudaGetSymbolAddress((void**)&xp, g_xp);
    cudaGetSymbolAddress((void**)&deg, g_deg);
    cudaGetSymbolAddress((void**)&dinv, g_dinv);
    cudaGetSymbolAddress((void**)&cnt, g_cnt);
    cudaGetSymbolAddress((void**)&cntp, g_cntp);
    cudaGetSymbolAddress((void**)&rowstart, g_rowstart);
    cudaGetSymbolAddress((void**)&cursor, g_cursor);
    cudaGetSymbolAddress((void**)&bsum, g_bsum);
    cudaGetSymbolAddress((void**)&dbins, g_dbins);
    cudaGetSymbolAddress((void**)&dcur, g_dcur);
    cudaGetSymbolAddress((void**)&perm, g_perm);
    cudaGetSymbolAddress((void**)&rank, g_rank);
    cudaGetSymbolAddress((void**)&adj, g_adj);
    cudaGetSymbolAddress((void**)&Wc, g_Wc);

    static int smem_set = 0;
    if (!smem_set) {
        cudaFuncSetAttribute(gemm_mma_kernel,
                             cudaFuncAttributeMaxDynamicSharedMemorySize, SM_TOTAL);
        smem_set = 1;
    }

    const size_t FB = (size_t)NN * DD;
    float* TB[7];
    for (int i = 0; i < 7; i++) TB[i] = Tbuf + (size_t)i * FB;

    const int T = 256;
    const int edgeBlocks = (EE + T - 1) / T;
    const int nodeBlocks = (NN + T - 1) / T;
    const int node1Blocks = (NN + 1 + T - 1) / T;
    const int propBlocks = (NN * 16 + T - 1) / T;
    const int gemmBlocks = (NN + 127) / 128;
    const int convwBlocks = (LL * KK * DD * DD + T - 1) / T;

    // --- setup ---
    cudaMemsetAsync(deg, 0, NN * sizeof(float));
    cudaMemsetAsync(cnt, 0, NN * sizeof(int));
    cudaMemsetAsync(dbins, 0, NBINS * sizeof(int));
    deg_hist_kernel<<<edgeBlocks, T>>>(src, dst, ew, deg, cnt);
    dinv_binhist_kernel<<<nodeBlocks, T>>>(deg, cnt, dinv, dbins);
    bin_scan_kernel<<<1, NBINS>>>(dbins, dcur);
    bin_scatter_kernel<<<nodeBlocks, T>>>(cnt, dcur, perm, rank, cntp);
    scan_block_kernel<<<SCAN_BLOCKS, SCAN_TPB>>>(cntp, rowstart, bsum);
    scan_sums_kernel<<<1, 128>>>(bsum);
    scan_add_kernel<<<node1Blocks, T>>>(rowstart, bsum, cursor);
    scatter_kernel<<<edgeBlocks, T>>>(src, dst, ew, dinv, rank, cursor, adj);
    permute_x_kernel<<<propBlocks, T>>>(x, perm, xp);
    convw_kernel<<<convwBlocks, T>>>(Wt, Wc);

    // --- layers ---
    const float* hin = xp;
    float* houts[3] = {out1, out2, (float*)d_out};

    for (int l = 0; l < LL; l++) {
        prop16_kernel<true><<<propBlocks, T>>>(hin, adj, rowstart, nullptr, TB[0]);
        for (int k = 2; k < KK; k++) {
            const float* tin = TB[k - 2];
            const float* t0 = (k == 2) ? hin : TB[k - 3];
            prop16_kernel<false><<<propBlocks, T>>>(tin, adj, rowstart, t0, TB[k - 1]);
        }
        TPtrs tsp;
        tsp.p[0] = hin;
        for (int k = 1; k < KK; k++) tsp.p[k] = TB[k - 1];
        const int* operm = (l == LL - 1) ? perm : nullptr;
        gemm_mma_kernel<<<gemmBlocks, 256, SM_TOTAL>>>(
            tsp, Wc + (size_t)l * KK * 2 * DD * DD, Bs + (size_t)l * DD,
            houts[l], operm);
        hin = houts[l];
    }
}